// round 9
// baseline (speedup 1.0000x reference)
#include <cuda_runtime.h>
#include <cstdint>

// Problem constants (fixed by the reference)
#define T_DIM 1024
#define B_DIM 256
#define I_DIM 256
#define H_DIM 256
#define M_DIM (T_DIM * B_DIM)

// Scratch for X = inputs @ W_xh + b_h  (fp32, 268 MB)
__device__ float g_X[(size_t)M_DIM * H_DIM];

// ---------------------------------------------------------------------------
// packed f32x2 helpers
// ---------------------------------------------------------------------------
__device__ __forceinline__ void ffma2(unsigned long long& d,
                                      unsigned long long a,
                                      unsigned long long b) {
    asm("fma.rn.f32x2 %0, %1, %2, %0;" : "+l"(d) : "l"(a), "l"(b));
}
__device__ __forceinline__ unsigned long long pk2(float lo, float hi) {
    unsigned long long d;
    asm("mov.b64 %0, {%1, %2};" : "=l"(d) : "f"(lo), "f"(hi));
    return d;
}
__device__ __forceinline__ float2 upk2(unsigned long long a) {
    float2 v;
    asm("mov.b64 {%0, %1}, %2;" : "=f"(v.x), "=f"(v.y) : "l"(a));
    return v;
}
__device__ __forceinline__ float hsum2(unsigned long long a) {
    float2 v = upk2(a);
    return v.x + v.y;
}
// bf16x2 (lo=even k, hi=odd k) -> f32x2 (lo, hi)
__device__ __forceinline__ unsigned long long bf2f2(uint32_t b) {
    uint32_t lo = b << 16;
    uint32_t hi = b & 0xffff0000u;
    unsigned long long d;
    asm("mov.b64 %0, {%1, %2};" : "=l"(d) : "r"(lo), "r"(hi));
    return d;
}
// pack two fp32 -> bf16x2 with lo=a, hi=b
__device__ __forceinline__ uint32_t f2bf2(float lo, float hi) {
    uint32_t d;
    asm("cvt.rn.bf16x2.f32 %0, %1, %2;" : "=r"(d) : "f"(hi), "f"(lo));
    return d;
}
// fast, accurate tanh: (e^{2x}-1) * rcp(e^{2x}+1)
__device__ __forceinline__ float fast_tanh(float x) {
    float e, r;
    asm("ex2.approx.f32 %0, %1;" : "=f"(e) : "f"(x * 2.8853900817779268f));
    asm("rcp.approx.f32 %0, %1;" : "=f"(r) : "f"(e + 1.0f));
    return (e - 1.0f) * r;
}

// ---------------------------------------------------------------------------
// Kernel 1: X = inputs @ W_xh + b_h  (UNCHANGED from round 8 — measured 640us)
// ---------------------------------------------------------------------------
#define BM 128
#define BN 128
#define BK 8
#define TM 8
#define TN 8
#define NKT (I_DIM / BK)
#define BROW 144

__global__ __launch_bounds__(256) void gemm_xh_kernel(
    const float* __restrict__ A,
    const float* __restrict__ Bw,
    const float* __restrict__ bias)
{
    __shared__ float As[2][BK * BM];
    __shared__ float Bs[2][BK * BROW];

    const int mTile = blockIdx.x;
    const int nTile = blockIdx.y;
    const int tid = threadIdx.x;

    const int tx = tid % (BN / TN);
    const int ty = tid / (BN / TN);

    const int aRow = tid >> 1;
    const int aCol = (tid & 1) * 4;
    const int bRow = tid >> 5;
    const int bCol = (tid & 31) * 4;
    const int bColP = bCol + 4 * (bCol >> 5);
    const int nRdP = 8 * tx + 4 * (tx >> 2);

    const float* Ag = A + (size_t)mTile * BM * I_DIM;
    const float* Bg = Bw + nTile * BN;

    unsigned long long acc2[4][TN];
#pragma unroll
    for (int i = 0; i < 4; i++)
#pragma unroll
        for (int j = 0; j < TN; j++) acc2[i][j] = 0ull;

    {
        float4 a = *(const float4*)&Ag[(size_t)aRow * I_DIM + aCol];
        As[0][(aCol + 0) * BM + aRow] = a.x;
        As[0][(aCol + 1) * BM + aRow] = a.y;
        As[0][(aCol + 2) * BM + aRow] = a.z;
        As[0][(aCol + 3) * BM + aRow] = a.w;
        float4 b = *(const float4*)&Bg[(size_t)bRow * H_DIM + bCol];
        *(float4*)&Bs[0][bRow * BROW + bColP] = b;
    }
    __syncthreads();

#pragma unroll 1
    for (int it = 0; it < NKT; it++) {
        const int cur = it & 1;
        float4 an, bn;
        if (it + 1 < NKT) {
            int k0 = (it + 1) * BK;
            an = *(const float4*)&Ag[(size_t)aRow * I_DIM + k0 + aCol];
            bn = *(const float4*)&Bg[(size_t)(k0 + bRow) * H_DIM + bCol];
        }

#pragma unroll
        for (int k = 0; k < BK; k++) {
            ulonglong2 am0 = *(const ulonglong2*)&As[cur][k * BM + ty * TM + 0];
            ulonglong2 am1 = *(const ulonglong2*)&As[cur][k * BM + ty * TM + 4];
            unsigned long long ap[4] = {am0.x, am0.y, am1.x, am1.y};
            float4 n0 = *(const float4*)&Bs[cur][k * BROW + nRdP + 0];
            float4 n1 = *(const float4*)&Bs[cur][k * BROW + nRdP + 4];
            unsigned long long bd[TN];
            bd[0] = pk2(n0.x, n0.x); bd[1] = pk2(n0.y, n0.y);
            bd[2] = pk2(n0.z, n0.z); bd[3] = pk2(n0.w, n0.w);
            bd[4] = pk2(n1.x, n1.x); bd[5] = pk2(n1.y, n1.y);
            bd[6] = pk2(n1.z, n1.z); bd[7] = pk2(n1.w, n1.w);
#pragma unroll
            for (int i = 0; i < 4; i++)
#pragma unroll
                for (int j = 0; j < TN; j++)
                    ffma2(acc2[i][j], ap[i], bd[j]);
        }

        if (it + 1 < NKT) {
            const int nxt = cur ^ 1;
            As[nxt][(aCol + 0) * BM + aRow] = an.x;
            As[nxt][(aCol + 1) * BM + aRow] = an.y;
            As[nxt][(aCol + 2) * BM + aRow] = an.z;
            As[nxt][(aCol + 3) * BM + aRow] = an.w;
            *(float4*)&Bs[nxt][bRow * BROW + bColP] = bn;
            __syncthreads();
        }
    }

    const int nBase = nTile * BN + tx * TN;
    float bv[TN];
#pragma unroll
    for (int j = 0; j < TN; j++) bv[j] = bias[nBase + j];

#pragma unroll
    for (int i = 0; i < 4; i++) {
        size_t row0 = (size_t)mTile * BM + ty * TM + 2 * i;
        float r0[TN], r1[TN];
#pragma unroll
        for (int j = 0; j < TN; j++) {
            float2 v = upk2(acc2[i][j]);
            r0[j] = v.x + bv[j];
            r1[j] = v.y + bv[j];
        }
        *(float4*)&g_X[row0 * H_DIM + nBase + 0] = make_float4(r0[0], r0[1], r0[2], r0[3]);
        *(float4*)&g_X[row0 * H_DIM + nBase + 4] = make_float4(r0[4], r0[5], r0[6], r0[7]);
        *(float4*)&g_X[(row0 + 1) * H_DIM + nBase + 0] = make_float4(r1[0], r1[1], r1[2], r1[3]);
        *(float4*)&g_X[(row0 + 1) * H_DIM + nBase + 4] = make_float4(r1[4], r1[5], r1[6], r1[7]);
    }
}

// ---------------------------------------------------------------------------
// Kernel 2: the recurrence — 1024 threads/CTA (8 warps/SMSP for phase overlap)
// Thread = (column-pair p = wid*4 + (lane&3) in 0..127, k-split s = lane>>2
// in 0..7, 32 k each). Per thread: 8 k fp32 weights in registers,
// 24 k bf16 weights in smem (conflict-free padded layout), packed f32x2 FMA.
// 4-shfl reduce-scatter over lane bits 2/3/4; lanes<16 finalize one output.
// Double-buffered 8-way-skewed state, one barrier per step.
// ---------------------------------------------------------------------------
#define SROW8 288                       // state row stride (256 data + 8x4 pad)
#define BUF8 (2 * SROW8)                // one buffer: 2 batch rows
#define WBLK_U32 40                     // 24 data u32 + 16 pad u32? (6 uint4 data + pad)
#define WPLANE_U32 (128 * WBLK_U32 + 4) // per-s plane stride (+16B skew pad)
#define RNN_SMEM_F (2 * BUF8 + 8 * WPLANE_U32)
#define RNN_SMEM_B (RNN_SMEM_F * 4)     // 168592 B < 227 KB

__global__ __launch_bounds__(1024, 1) void rnn_kernel(
    const float* __restrict__ W,      // W_hh [k][h]
    float* __restrict__ out,          // outputs [T,B,H] (+ optional state [B,H])
    int write_state)
{
    extern __shared__ float sm[];
    float* S0 = sm;                         // state buffer A
    float* S1 = sm + BUF8;                  // state buffer B
    uint32_t* WB = (uint32_t*)(sm + 2 * BUF8);

    const int tid = threadIdx.x;
    const int wid = tid >> 5;
    const int lane = tid & 31;
    const int p = wid * 4 + (lane & 3);     // column pair 0..127
    const int s = lane >> 2;                // k-split 0..7
    const int h0 = 2 * p;
    const int kbase = 32 * s;
    const int bidx0 = blockIdx.x * 2;
    const int sb0 = (s & 1);                // output column parity
    const int sb1 = (s >> 1) & 1;           // output row
    const bool writer = (lane < 16);        // s < 4

    // register-resident fp32 weights: k in [kbase, kbase+8), packed (k, k+1)
    unsigned long long wrA[4], wrB[4];
#pragma unroll
    for (int j = 0; j < 4; j++) {
        int k = kbase + 2 * j;
        float2 wk  = *(const float2*)&W[(size_t)k * H_DIM + h0];
        float2 wk1 = *(const float2*)&W[(size_t)(k + 1) * H_DIM + h0];
        wrA[j] = pk2(wk.x, wk1.x);
        wrB[j] = pk2(wk.y, wk1.y);
    }

    // smem-resident bf16 weights: k in [kbase+8, kbase+32)
    // uint4 j2 (j2=0..5): {colA pair(k), colB pair(k), colA pair(k+2), colB pair(k+2)}
    // with k = kbase + 8 + 4*j2
    uint32_t* myWB = WB + s * WPLANE_U32 + p * WBLK_U32;
#pragma unroll
    for (int j2 = 0; j2 < 6; j2++) {
        int k = kbase + 8 + 4 * j2;
        float2 wk0 = *(const float2*)&W[(size_t)k * H_DIM + h0];
        float2 wk1 = *(const float2*)&W[(size_t)(k + 1) * H_DIM + h0];
        float2 wk2 = *(const float2*)&W[(size_t)(k + 2) * H_DIM + h0];
        float2 wk3 = *(const float2*)&W[(size_t)(k + 3) * H_DIM + h0];
        myWB[4 * j2 + 0] = f2bf2(wk0.x, wk1.x);
        myWB[4 * j2 + 1] = f2bf2(wk0.y, wk1.y);
        myWB[4 * j2 + 2] = f2bf2(wk2.x, wk3.x);
        myWB[4 * j2 + 3] = f2bf2(wk2.y, wk3.y);
    }

    // zero both state buffers (incl. pads)
    for (int i = tid; i < 2 * BUF8; i += 1024) sm[i] = 0.0f;
    __syncthreads();

    const uint4* wq = (const uint4*)myWB;    // 6 entries
    // skewed state base for this split: 32 data floats + 4 pad per split
    const int soff = 36 * s;
    // per-thread output addresses
    const int hpw = (h0 + sb0) + 4 * ((h0 + sb0) >> 5);    // skewed index of h
    const int stoff = sb1 * SROW8 + hpw;
    const size_t goff = (size_t)(bidx0 + sb1) * H_DIM + h0 + sb0;
    float* outp = out + goff;
    const float* xp = g_X + goff;
    float* state_out = out + (size_t)T_DIM * B_DIM * H_DIM + goff;

    float x_nxt = *xp;   // x(t=0)

    auto step = [&](int t, const float* Sr, float* Sw) {
        const ulonglong2* su0 = (const ulonglong2*)(Sr + soff);          // row 0
        const ulonglong2* su1 = (const ulonglong2*)(Sr + SROW8 + soff);  // row 1

        float x_cur = x_nxt;
        int tn = (t + 1 < T_DIM) ? (t + 1) : t;
        x_nxt = xp[(size_t)tn * (B_DIM * H_DIM)];

        unsigned long long a00 = 0ull, a01 = 0ull, a10 = 0ull, a11 = 0ull;

        // fp32 register half: k offsets [0,8)
#pragma unroll
        for (int j = 0; j < 2; j++) {
            ulonglong2 s0 = su0[j];
            ulonglong2 s1 = su1[j];
            ffma2(a00, s0.x, wrA[2 * j]);     ffma2(a01, s0.x, wrB[2 * j]);
            ffma2(a00, s0.y, wrA[2 * j + 1]); ffma2(a01, s0.y, wrB[2 * j + 1]);
            ffma2(a10, s1.x, wrA[2 * j]);     ffma2(a11, s1.x, wrB[2 * j]);
            ffma2(a10, s1.y, wrA[2 * j + 1]); ffma2(a11, s1.y, wrB[2 * j + 1]);
        }
        // bf16 smem half: k offsets [8,32)
#pragma unroll
        for (int j2 = 0; j2 < 6; j2++) {
            uint4 q = wq[j2];
            unsigned long long wA0 = bf2f2(q.x);
            unsigned long long wB0 = bf2f2(q.y);
            unsigned long long wA1 = bf2f2(q.z);
            unsigned long long wB1 = bf2f2(q.w);
            ulonglong2 s0 = su0[2 + j2];
            ulonglong2 s1 = su1[2 + j2];
            ffma2(a00, s0.x, wA0); ffma2(a01, s0.x, wB0);
            ffma2(a00, s0.y, wA1); ffma2(a01, s0.y, wB1);
            ffma2(a10, s1.x, wA0); ffma2(a11, s1.x, wB0);
            ffma2(a10, s1.y, wA1); ffma2(a11, s1.y, wB1);
        }

        float f00 = hsum2(a00), f01 = hsum2(a01);
        float f10 = hsum2(a10), f11 = hsum2(a11);

        // reduce-scatter over 8 k-splits (lane bits 2,3,4 = s bits 0,1,2)
        float m0 = sb0 ? f01 : f00;       // row0, col h0+sb0
        float m1 = sb0 ? f11 : f10;       // row1
        float o0 = sb0 ? f00 : f01;
        float o1 = sb0 ? f10 : f11;
        m0 += __shfl_xor_sync(0xffffffffu, o0, 4);
        m1 += __shfl_xor_sync(0xffffffffu, o1, 4);
        float mm = sb1 ? m1 : m0;
        float oo = sb1 ? m0 : m1;
        mm += __shfl_xor_sync(0xffffffffu, oo, 8);
        mm += __shfl_xor_sync(0xffffffffu, mm, 16);

        float h = fast_tanh(mm + x_cur);

        if (writer) {
            Sw[stoff] = h;
            outp[(size_t)t * (B_DIM * H_DIM)] = h;
        }

        __syncthreads();
    };

#pragma unroll 1
    for (int t = 0; t < T_DIM; t += 2) {
        step(t,     S0, S1);
        step(t + 1, S1, S0);
    }

    if (write_state && writer) *state_out = S0[stoff];
}

// ---------------------------------------------------------------------------
// Launch
// ---------------------------------------------------------------------------
extern "C" void kernel_launch(void* const* d_in, const int* in_sizes, int n_in,
                              void* d_out, int out_size)
{
    (void)n_in; (void)in_sizes;
    const float* inputs = (const float*)d_in[0];  // [T,B,I]
    const float* W_xh   = (const float*)d_in[1];  // [I,H]
    const float* W_hh   = (const float*)d_in[2];  // [H,H]
    const float* b_h    = (const float*)d_in[3];  // [H]
    float* out = (float*)d_out;

    const long long need = (long long)T_DIM * B_DIM * H_DIM + (long long)B_DIM * H_DIM;
    int write_state = ((long long)out_size >= need) ? 1 : 0;

    dim3 g1(M_DIM / BM, H_DIM / BN);
    gemm_xh_kernel<<<g1, 256>>>(inputs, W_xh, b_h);

    cudaFuncSetAttribute(rnn_kernel, cudaFuncAttributeMaxDynamicSharedMemorySize,
                         RNN_SMEM_B);
    rnn_kernel<<<B_DIM / 2, 1024, RNN_SMEM_B>>>(W_hh, out, write_state);
}

// round 10
// speedup vs baseline: 1.0195x; 1.0195x over previous
#include <cuda_runtime.h>
#include <cuda_bf16.h>
#include <mma.h>
#include <cstdint>

using namespace nvcuda;

// Problem constants (fixed by the reference)
#define T_DIM 1024
#define B_DIM 256
#define I_DIM 256
#define H_DIM 256
#define M_DIM (T_DIM * B_DIM)

// Scratch for X = inputs @ W_xh + b_h  (fp32, 268 MB)
__device__ float g_X[(size_t)M_DIM * H_DIM];

// ---------------------------------------------------------------------------
// packed f32x2 helpers
// ---------------------------------------------------------------------------
__device__ __forceinline__ void ffma2(unsigned long long& d,
                                      unsigned long long a,
                                      unsigned long long b) {
    asm("fma.rn.f32x2 %0, %1, %2, %0;" : "+l"(d) : "l"(a), "l"(b));
}
__device__ __forceinline__ unsigned long long pk2(float lo, float hi) {
    unsigned long long d;
    asm("mov.b64 %0, {%1, %2};" : "=l"(d) : "f"(lo), "f"(hi));
    return d;
}
__device__ __forceinline__ float2 upk2(unsigned long long a) {
    float2 v;
    asm("mov.b64 {%0, %1}, %2;" : "=f"(v.x), "=f"(v.y) : "l"(a));
    return v;
}
__device__ __forceinline__ float hsum2(unsigned long long a) {
    float2 v = upk2(a);
    return v.x + v.y;
}
__device__ __forceinline__ unsigned long long bf2f2(uint32_t b) {
    uint32_t lo = b << 16;
    uint32_t hi = b & 0xffff0000u;
    unsigned long long d;
    asm("mov.b64 %0, {%1, %2};" : "=l"(d) : "r"(lo), "r"(hi));
    return d;
}
__device__ __forceinline__ uint32_t f2bf2(float lo, float hi) {
    uint32_t d;
    asm("cvt.rn.bf16x2.f32 %0, %1, %2;" : "=r"(d) : "f"(hi), "f"(lo));
    return d;
}
__device__ __forceinline__ float fast_tanh(float x) {
    float e, r;
    asm("ex2.approx.f32 %0, %1;" : "=f"(e) : "f"(x * 2.8853900817779268f));
    asm("rcp.approx.f32 %0, %1;" : "=f"(r) : "f"(e + 1.0f));
    return (e - 1.0f) * r;
}

// ---------------------------------------------------------------------------
// Kernel 1: X = inputs @ W_xh + b_h  — TENSOR CORES (wmma bf16, 3-term split)
// X ~= Ahi*Whi + Ahi*Wlo + Alo*Whi  (fp32 accumulate; lo*lo dropped, ~2^-18)
// CTA: 256 thr (8 warps), tile 128x128; warp = 32x64 = 2x4 wmma 16x16 tiles.
// Per 16-wide k-chunk: fp32 tiles loaded, split hi/lo bf16 into smem inline.
// Bias folded in by initializing accumulator fragments from a replicated tile.
// ---------------------------------------------------------------------------
#define GBM 128
#define GBN 128
#define GBK 16
#define ALD 24     // sAhi/sAlo leading dim (16 data + 8 pad bf16)
#define BLD 136    // sBhi/sBlo leading dim (128 data + 8 pad bf16)

__global__ __launch_bounds__(256) void gemm_xh_tc(
    const float* __restrict__ A,     // [M_DIM, I_DIM]
    const float* __restrict__ Bw,    // [I_DIM, H_DIM]
    const float* __restrict__ bias)  // [H_DIM]
{
    __shared__ __nv_bfloat16 sAhi[GBM][ALD];
    __shared__ __nv_bfloat16 sAlo[GBM][ALD];
    __shared__ __nv_bfloat16 sBhi[GBK][BLD];
    __shared__ __nv_bfloat16 sBlo[GBK][BLD];
    __shared__ float sBias[16][BLD];

    const int mTile = blockIdx.x;
    const int nTile = blockIdx.y;
    const int tid = threadIdx.x;
    const int wid = tid >> 5;
    const int wm = wid & 3;          // 0..3 : 32-row block
    const int wn = wid >> 2;         // 0..1 : 64-col block

    // A-load mapping: 128 rows x 16 cols, 8 fp32 per thread
    const int aRow = tid >> 1;
    const int aCol = (tid & 1) * 8;
    // B-load mapping: 16 rows x 128 cols, 8 fp32 per thread
    const int bRow = tid >> 4;
    const int bCol = (tid & 15) * 8;

    const float* Ag = A + (size_t)mTile * GBM * I_DIM;
    const float* Bg = Bw + nTile * GBN;

    // bias tile: every row identical
    for (int idx = tid; idx < 16 * GBN; idx += 256) {
        int r = idx >> 7, c = idx & 127;
        sBias[r][c] = bias[nTile * GBN + c];
    }
    __syncthreads();

    wmma::fragment<wmma::accumulator, 16, 16, 16, float> acc[2][4];
#pragma unroll
    for (int i = 0; i < 2; i++)
#pragma unroll
        for (int j = 0; j < 4; j++)
            wmma::load_matrix_sync(acc[i][j], &sBias[0][wn * 64 + j * 16], BLD,
                                   wmma::mem_row_major);
    __syncthreads();

#pragma unroll 1
    for (int kt = 0; kt < I_DIM / GBK; kt++) {
        const int k0 = kt * GBK;

        // global loads (before barrier, overlap with previous compute drain)
        float4 a0 = *(const float4*)&Ag[(size_t)aRow * I_DIM + k0 + aCol];
        float4 a1 = *(const float4*)&Ag[(size_t)aRow * I_DIM + k0 + aCol + 4];
        float4 b0 = *(const float4*)&Bg[(size_t)(k0 + bRow) * H_DIM + bCol];
        float4 b1 = *(const float4*)&Bg[(size_t)(k0 + bRow) * H_DIM + bCol + 4];

        __syncthreads();   // previous iteration's fragment loads complete

        // split-convert and store to smem
        float av[8] = {a0.x, a0.y, a0.z, a0.w, a1.x, a1.y, a1.z, a1.w};
        float bv[8] = {b0.x, b0.y, b0.z, b0.w, b1.x, b1.y, b1.z, b1.w};
#pragma unroll
        for (int e = 0; e < 8; e++) {
            __nv_bfloat16 h = __float2bfloat16(av[e]);
            sAhi[aRow][aCol + e] = h;
            sAlo[aRow][aCol + e] = __float2bfloat16(av[e] - __bfloat162float(h));
        }
#pragma unroll
        for (int e = 0; e < 8; e++) {
            __nv_bfloat16 h = __float2bfloat16(bv[e]);
            sBhi[bRow][bCol + e] = h;
            sBlo[bRow][bCol + e] = __float2bfloat16(bv[e] - __bfloat162float(h));
        }
        __syncthreads();

        wmma::fragment<wmma::matrix_a, 16, 16, 16, __nv_bfloat16, wmma::row_major> afh[2], afl[2];
        wmma::fragment<wmma::matrix_b, 16, 16, 16, __nv_bfloat16, wmma::row_major> bfh[4], bfl[4];
#pragma unroll
        for (int i = 0; i < 2; i++) {
            wmma::load_matrix_sync(afh[i], &sAhi[wm * 32 + i * 16][0], ALD);
            wmma::load_matrix_sync(afl[i], &sAlo[wm * 32 + i * 16][0], ALD);
        }
#pragma unroll
        for (int j = 0; j < 4; j++) {
            wmma::load_matrix_sync(bfh[j], &sBhi[0][wn * 64 + j * 16], BLD);
            wmma::load_matrix_sync(bfl[j], &sBlo[0][wn * 64 + j * 16], BLD);
        }
#pragma unroll
        for (int i = 0; i < 2; i++)
#pragma unroll
            for (int j = 0; j < 4; j++) {
                wmma::mma_sync(acc[i][j], afh[i], bfh[j], acc[i][j]);
                wmma::mma_sync(acc[i][j], afh[i], bfl[j], acc[i][j]);
                wmma::mma_sync(acc[i][j], afl[i], bfh[j], acc[i][j]);
            }
    }

    // store accumulators (bias already folded in)
#pragma unroll
    for (int i = 0; i < 2; i++)
#pragma unroll
        for (int j = 0; j < 4; j++) {
            size_t row0 = (size_t)mTile * GBM + wm * 32 + i * 16;
            int col0 = nTile * GBN + wn * 64 + j * 16;
            wmma::store_matrix_sync(&g_X[row0 * H_DIM + col0], acc[i][j], H_DIM,
                                    wmma::mem_row_major);
        }
}

// ---------------------------------------------------------------------------
// Kernel 2: the recurrence — EXACT round-8 version (measured 1090us).
// ---------------------------------------------------------------------------
#define SROW 272
#define BUF_F (2 * SROW)
#define PAIR_STRIDE_U32 36
#define SPLIT_STRIDE_U32 (128 * PAIR_STRIDE_U32 + 4)
#define SMEM_STATE_F (2 * BUF_F)
#define RNN_SMEM_F (SMEM_STATE_F + 4 * SPLIT_STRIDE_U32)
#define RNN_SMEM_B (RNN_SMEM_F * 4)

__global__ __launch_bounds__(512, 1) void rnn_kernel(
    const float* __restrict__ W,
    float* __restrict__ out,
    int write_state)
{
    extern __shared__ float sm[];
    float* S0 = sm;
    float* S1 = sm + BUF_F;
    uint32_t* WB = (uint32_t*)(sm + SMEM_STATE_F);

    const int tid = threadIdx.x;
    const int wid = tid >> 5;
    const int lane = tid & 31;
    const int p = wid * 8 + (lane & 7);
    const int s = lane >> 3;
    const int h0 = 2 * p;
    const int kbase = 64 * s;
    const int bidx0 = blockIdx.x * 2;
    const int hs = h0 + ((h0 >> 6) << 2);
    const bool sb0 = (s & 1);
    const int sb1 = (s >> 1);

    unsigned long long wrA[16], wrB[16];
#pragma unroll
    for (int j = 0; j < 16; j++) {
        int k = kbase + 2 * j;
        float2 wk  = *(const float2*)&W[(size_t)k * H_DIM + h0];
        float2 wk1 = *(const float2*)&W[(size_t)(k + 1) * H_DIM + h0];
        wrA[j] = pk2(wk.x, wk1.x);
        wrB[j] = pk2(wk.y, wk1.y);
    }

    uint32_t* myWB = WB + s * SPLIT_STRIDE_U32 + p * PAIR_STRIDE_U32;
#pragma unroll
    for (int j = 0; j < 16; j++) {
        int k = kbase + 32 + 2 * j;
        float2 wk  = *(const float2*)&W[(size_t)k * H_DIM + h0];
        float2 wk1 = *(const float2*)&W[(size_t)(k + 1) * H_DIM + h0];
        myWB[2 * j]     = f2bf2(wk.x, wk1.x);
        myWB[2 * j + 1] = f2bf2(wk.y, wk1.y);
    }

    for (int i = tid; i < SMEM_STATE_F; i += 512) sm[i] = 0.0f;
    __syncthreads();

    const uint4* wq = (const uint4*)myWB;
    const int stoff = sb1 * SROW + hs + (sb0 ? 1 : 0);
    const size_t goff = (size_t)(bidx0 + sb1) * H_DIM + h0 + (sb0 ? 1 : 0);
    float* outp = out + goff;
    const float* xp = g_X + goff;
    float* state_out = out + (size_t)T_DIM * B_DIM * H_DIM + goff;

    float x_nxt = *xp;

    auto step = [&](int t, const float* Sr, float* Sw) {
        const ulonglong2* su0 = (const ulonglong2*)(Sr + 68 * s);
        const ulonglong2* su1 = (const ulonglong2*)(Sr + SROW + 68 * s);

        float x_cur = x_nxt;
        int tn = (t + 1 < T_DIM) ? (t + 1) : t;
        x_nxt = xp[(size_t)tn * (B_DIM * H_DIM)];

        unsigned long long a00 = 0ull, a01 = 0ull, a10 = 0ull, a11 = 0ull;

#pragma unroll
        for (int j2 = 0; j2 < 8; j2++) {
            ulonglong2 s0 = su0[j2];
            ulonglong2 s1 = su1[j2];
            ffma2(a00, s0.x, wrA[2 * j2]);     ffma2(a01, s0.x, wrB[2 * j2]);
            ffma2(a00, s0.y, wrA[2 * j2 + 1]); ffma2(a01, s0.y, wrB[2 * j2 + 1]);
            ffma2(a10, s1.x, wrA[2 * j2]);     ffma2(a11, s1.x, wrB[2 * j2]);
            ffma2(a10, s1.y, wrA[2 * j2 + 1]); ffma2(a11, s1.y, wrB[2 * j2 + 1]);
        }
#pragma unroll
        for (int j2 = 0; j2 < 8; j2++) {
            uint4 q = wq[j2];
            unsigned long long wA0 = bf2f2(q.x);
            unsigned long long wB0 = bf2f2(q.y);
            unsigned long long wA1 = bf2f2(q.z);
            unsigned long long wB1 = bf2f2(q.w);
            ulonglong2 s0 = su0[8 + j2];
            ulonglong2 s1 = su1[8 + j2];
            ffma2(a00, s0.x, wA0); ffma2(a01, s0.x, wB0);
            ffma2(a00, s0.y, wA1); ffma2(a01, s0.y, wB1);
            ffma2(a10, s1.x, wA0); ffma2(a11, s1.x, wB0);
            ffma2(a10, s1.y, wA1); ffma2(a11, s1.y, wB1);
        }

        float f00 = hsum2(a00), f01 = hsum2(a01);
        float f10 = hsum2(a10), f11 = hsum2(a11);

        float m0 = sb0 ? f01 : f00;
        float m1 = sb0 ? f11 : f10;
        float o0 = sb0 ? f00 : f01;
        float o1 = sb0 ? f10 : f11;
        m0 += __shfl_xor_sync(0xffffffffu, o0, 8);
        m1 += __shfl_xor_sync(0xffffffffu, o1, 8);
        float mm = sb1 ? m1 : m0;
        float oo = sb1 ? m0 : m1;
        mm += __shfl_xor_sync(0xffffffffu, oo, 16);

        float h = fast_tanh(mm + x_cur);

        Sw[stoff] = h;
        outp[(size_t)t * (B_DIM * H_DIM)] = h;

        __syncthreads();
    };

#pragma unroll 1
    for (int t = 0; t < T_DIM; t += 2) {
        step(t,     S0, S1);
        step(t + 1, S1, S0);
    }

    if (write_state) *state_out = S0[stoff];
}

// ---------------------------------------------------------------------------
// Launch
// ---------------------------------------------------------------------------
extern "C" void kernel_launch(void* const* d_in, const int* in_sizes, int n_in,
                              void* d_out, int out_size)
{
    (void)n_in; (void)in_sizes;
    const float* inputs = (const float*)d_in[0];  // [T,B,I]
    const float* W_xh   = (const float*)d_in[1];  // [I,H]
    const float* W_hh   = (const float*)d_in[2];  // [H,H]
    const float* b_h    = (const float*)d_in[3];  // [H]
    float* out = (float*)d_out;

    const long long need = (long long)T_DIM * B_DIM * H_DIM + (long long)B_DIM * H_DIM;
    int write_state = ((long long)out_size >= need) ? 1 : 0;

    dim3 g1(M_DIM / GBM, H_DIM / GBN);
    gemm_xh_tc<<<g1, 256>>>(inputs, W_xh, b_h);

    cudaFuncSetAttribute(rnn_kernel, cudaFuncAttributeMaxDynamicSharedMemorySize,
                         RNN_SMEM_B);
    rnn_kernel<<<B_DIM / 2, 512, RNN_SMEM_B>>>(W_hh, out, write_state);
}

// round 11
// speedup vs baseline: 1.1163x; 1.0949x over previous
#include <cuda_runtime.h>
#include <cuda_bf16.h>
#include <mma.h>
#include <cstdint>

using namespace nvcuda;

// Problem constants (fixed by the reference)
#define T_DIM 1024
#define B_DIM 256
#define I_DIM 256
#define H_DIM 256
#define M_DIM (T_DIM * B_DIM)

// Scratch for X = inputs @ W_xh + b_h  (fp32, 268 MB)
__device__ float g_X[(size_t)M_DIM * H_DIM];

// ---------------------------------------------------------------------------
// packed helpers
// ---------------------------------------------------------------------------
__device__ __forceinline__ void ffma2(unsigned long long& d,
                                      unsigned long long a,
                                      unsigned long long b) {
    asm("fma.rn.f32x2 %0, %1, %2, %0;" : "+l"(d) : "l"(a), "l"(b));
}
__device__ __forceinline__ unsigned long long pk2(float lo, float hi) {
    unsigned long long d;
    asm("mov.b64 %0, {%1, %2};" : "=l"(d) : "f"(lo), "f"(hi));
    return d;
}
__device__ __forceinline__ float2 upk2(unsigned long long a) {
    float2 v;
    asm("mov.b64 {%0, %1}, %2;" : "=f"(v.x), "=f"(v.y) : "l"(a));
    return v;
}
__device__ __forceinline__ float hsum2(unsigned long long a) {
    float2 v = upk2(a);
    return v.x + v.y;
}
__device__ __forceinline__ unsigned long long bf2f2(uint32_t b) {
    uint32_t lo = b << 16;
    uint32_t hi = b & 0xffff0000u;
    unsigned long long d;
    asm("mov.b64 %0, {%1, %2};" : "=l"(d) : "r"(lo), "r"(hi));
    return d;
}
__device__ __forceinline__ uint32_t f2bf2(float lo, float hi) {
    uint32_t d;
    asm("cvt.rn.bf16x2.f32 %0, %1, %2;" : "=r"(d) : "f"(hi), "f"(lo));
    return d;
}
__device__ __forceinline__ float fast_tanh(float x) {
    float e, r;
    asm("ex2.approx.f32 %0, %1;" : "=f"(e) : "f"(x * 2.8853900817779268f));
    asm("rcp.approx.f32 %0, %1;" : "=f"(r) : "f"(e + 1.0f));
    return (e - 1.0f) * r;
}

// split 16 consecutive fp32 -> 8 bf16x2 hi + 8 bf16x2 lo, written as 2+2 uint4
__device__ __forceinline__ void split16(const float* v, uint4* hiOut, uint4* loOut) {
    uint32_t h[8], l[8];
#pragma unroll
    for (int j = 0; j < 8; j++) {
        float a0 = v[2 * j], a1 = v[2 * j + 1];
        uint32_t hp = f2bf2(a0, a1);
        float2 hv = upk2(bf2f2(hp));
        l[j] = f2bf2(a0 - hv.x, a1 - hv.y);
        h[j] = hp;
    }
    hiOut[0] = make_uint4(h[0], h[1], h[2], h[3]);
    hiOut[1] = make_uint4(h[4], h[5], h[6], h[7]);
    loOut[0] = make_uint4(l[0], l[1], l[2], l[3]);
    loOut[1] = make_uint4(l[4], l[5], l[6], l[7]);
}

// ---------------------------------------------------------------------------
// Kernel 1: X = inputs @ W_xh + b_h  — wmma bf16 3-term split, packed converts
// X ~= Ahi*Whi + Ahi*Wlo + Alo*Whi  (fp32 accumulate; lo*lo term ~2^-18 dropped)
// CTA 256 thr, tile 128x128, GBK=32. Vectorized STS.128 for converted tiles.
// Bias folded via accumulator init from an smem tile overlaid on sAhi/sAlo.
// ---------------------------------------------------------------------------
#define GBM 128
#define GBN 128
#define GBK 32
#define ALD 48     // A tile leading dim (32 data + 16 pad bf16); 96B rows (16B-aligned)
#define BLD 136    // B tile leading dim (128 data + 8 pad bf16); 272B rows

__global__ __launch_bounds__(256) void gemm_xh_tc(
    const float* __restrict__ A,     // [M_DIM, I_DIM]
    const float* __restrict__ Bw,    // [I_DIM, H_DIM]
    const float* __restrict__ bias)  // [H_DIM]
{
    __shared__ __nv_bfloat16 sAhi[GBM][ALD];     // 12 KB
    __shared__ __nv_bfloat16 sAlo[GBM][ALD];     // 12 KB
    __shared__ __nv_bfloat16 sBhi[GBK][BLD];     // 8.5 KB
    __shared__ __nv_bfloat16 sBlo[GBK][BLD];     // 8.5 KB

    const int mTile = blockIdx.x;
    const int nTile = blockIdx.y;
    const int tid = threadIdx.x;
    const int wid = tid >> 5;
    const int wm = wid & 3;          // 32-row block
    const int wn = wid >> 2;         // 64-col block

    // A tile: 128 rows x 32 cols; thread loads 16 floats
    const int aRow = tid >> 1;
    const int aCol = (tid & 1) * 16;
    // B tile: 32 rows x 128 cols; thread loads 16 floats
    const int bRow = tid >> 3;
    const int bCol = (tid & 7) * 16;

    const float* Ag = A + (size_t)mTile * GBM * I_DIM;
    const float* Bg = Bw + nTile * GBN;

    // ---- bias -> accumulator init (bias tile overlaid on sAhi/sAlo space)
    float* sBiasF = (float*)&sAhi[0][0];   // 16 x BLD floats = 8.5 KB (fits in 12 KB)
    for (int idx = tid; idx < 16 * GBN; idx += 256) {
        int r = idx >> 7, c = idx & 127;
        sBiasF[r * BLD + c] = bias[nTile * GBN + c];
    }
    __syncthreads();

    wmma::fragment<wmma::accumulator, 16, 16, 16, float> acc[2][4];
#pragma unroll
    for (int i = 0; i < 2; i++)
#pragma unroll
        for (int j = 0; j < 4; j++)
            wmma::load_matrix_sync(acc[i][j], &sBiasF[wn * 64 + j * 16], BLD,
                                   wmma::mem_row_major);
    __syncthreads();

#pragma unroll 1
    for (int kt = 0; kt < I_DIM / GBK; kt++) {
        const int k0 = kt * GBK;

        // global loads (issue before barrier; overlap previous compute drain)
        float av[16], bv[16];
        *(float4*)&av[0]  = *(const float4*)&Ag[(size_t)aRow * I_DIM + k0 + aCol + 0];
        *(float4*)&av[4]  = *(const float4*)&Ag[(size_t)aRow * I_DIM + k0 + aCol + 4];
        *(float4*)&av[8]  = *(const float4*)&Ag[(size_t)aRow * I_DIM + k0 + aCol + 8];
        *(float4*)&av[12] = *(const float4*)&Ag[(size_t)aRow * I_DIM + k0 + aCol + 12];
        *(float4*)&bv[0]  = *(const float4*)&Bg[(size_t)(k0 + bRow) * H_DIM + bCol + 0];
        *(float4*)&bv[4]  = *(const float4*)&Bg[(size_t)(k0 + bRow) * H_DIM + bCol + 4];
        *(float4*)&bv[8]  = *(const float4*)&Bg[(size_t)(k0 + bRow) * H_DIM + bCol + 8];
        *(float4*)&bv[12] = *(const float4*)&Bg[(size_t)(k0 + bRow) * H_DIM + bCol + 12];

        __syncthreads();   // previous iteration's fragment loads complete

        // packed split-convert + vector stores (2+2 STS.128 per operand)
        split16(av, (uint4*)&sAhi[aRow][aCol], (uint4*)&sAlo[aRow][aCol]);
        split16(bv, (uint4*)&sBhi[bRow][bCol], (uint4*)&sBlo[bRow][bCol]);
        __syncthreads();

#pragma unroll
        for (int ks = 0; ks < 2; ks++) {
            wmma::fragment<wmma::matrix_a, 16, 16, 16, __nv_bfloat16, wmma::row_major> afh[2], afl[2];
            wmma::fragment<wmma::matrix_b, 16, 16, 16, __nv_bfloat16, wmma::row_major> bfh[4], bfl[4];
#pragma unroll
            for (int i = 0; i < 2; i++) {
                wmma::load_matrix_sync(afh[i], &sAhi[wm * 32 + i * 16][ks * 16], ALD);
                wmma::load_matrix_sync(afl[i], &sAlo[wm * 32 + i * 16][ks * 16], ALD);
            }
#pragma unroll
            for (int j = 0; j < 4; j++) {
                wmma::load_matrix_sync(bfh[j], &sBhi[ks * 16][wn * 64 + j * 16], BLD);
                wmma::load_matrix_sync(bfl[j], &sBlo[ks * 16][wn * 64 + j * 16], BLD);
            }
#pragma unroll
            for (int i = 0; i < 2; i++)
#pragma unroll
                for (int j = 0; j < 4; j++) {
                    wmma::mma_sync(acc[i][j], afh[i], bfh[j], acc[i][j]);
                    wmma::mma_sync(acc[i][j], afh[i], bfl[j], acc[i][j]);
                    wmma::mma_sync(acc[i][j], afl[i], bfh[j], acc[i][j]);
                }
        }
    }

    // store accumulators (bias already folded in)
#pragma unroll
    for (int i = 0; i < 2; i++)
#pragma unroll
        for (int j = 0; j < 4; j++) {
            size_t row0 = (size_t)mTile * GBM + wm * 32 + i * 16;
            int col0 = nTile * GBN + wn * 64 + j * 16;
            wmma::store_matrix_sync(&g_X[row0 * H_DIM + col0], acc[i][j], H_DIM,
                                    wmma::mem_row_major);
        }
}

// ---------------------------------------------------------------------------
// Kernel 2: the recurrence — EXACT round-8 version (measured ~1090us).
// ---------------------------------------------------------------------------
#define SROW 272
#define BUF_F (2 * SROW)
#define PAIR_STRIDE_U32 36
#define SPLIT_STRIDE_U32 (128 * PAIR_STRIDE_U32 + 4)
#define SMEM_STATE_F (2 * BUF_F)
#define RNN_SMEM_F (SMEM_STATE_F + 4 * SPLIT_STRIDE_U32)
#define RNN_SMEM_B (RNN_SMEM_F * 4)

__global__ __launch_bounds__(512, 1) void rnn_kernel(
    const float* __restrict__ W,
    float* __restrict__ out,
    int write_state)
{
    extern __shared__ float sm[];
    float* S0 = sm;
    float* S1 = sm + BUF_F;
    uint32_t* WB = (uint32_t*)(sm + SMEM_STATE_F);

    const int tid = threadIdx.x;
    const int wid = tid >> 5;
    const int lane = tid & 31;
    const int p = wid * 8 + (lane & 7);
    const int s = lane >> 3;
    const int h0 = 2 * p;
    const int kbase = 64 * s;
    const int bidx0 = blockIdx.x * 2;
    const int hs = h0 + ((h0 >> 6) << 2);
    const bool sb0 = (s & 1);
    const int sb1 = (s >> 1);

    unsigned long long wrA[16], wrB[16];
#pragma unroll
    for (int j = 0; j < 16; j++) {
        int k = kbase + 2 * j;
        float2 wk  = *(const float2*)&W[(size_t)k * H_DIM + h0];
        float2 wk1 = *(const float2*)&W[(size_t)(k + 1) * H_DIM + h0];
        wrA[j] = pk2(wk.x, wk1.x);
        wrB[j] = pk2(wk.y, wk1.y);
    }

    uint32_t* myWB = WB + s * SPLIT_STRIDE_U32 + p * PAIR_STRIDE_U32;
#pragma unroll
    for (int j = 0; j < 16; j++) {
        int k = kbase + 32 + 2 * j;
        float2 wk  = *(const float2*)&W[(size_t)k * H_DIM + h0];
        float2 wk1 = *(const float2*)&W[(size_t)(k + 1) * H_DIM + h0];
        myWB[2 * j]     = f2bf2(wk.x, wk1.x);
        myWB[2 * j + 1] = f2bf2(wk.y, wk1.y);
    }

    for (int i = tid; i < SMEM_STATE_F; i += 512) sm[i] = 0.0f;
    __syncthreads();

    const uint4* wq = (const uint4*)myWB;
    const int stoff = sb1 * SROW + hs + (sb0 ? 1 : 0);
    const size_t goff = (size_t)(bidx0 + sb1) * H_DIM + h0 + (sb0 ? 1 : 0);
    float* outp = out + goff;
    const float* xp = g_X + goff;
    float* state_out = out + (size_t)T_DIM * B_DIM * H_DIM + goff;

    float x_nxt = *xp;

    auto step = [&](int t, const float* Sr, float* Sw) {
        const ulonglong2* su0 = (const ulonglong2*)(Sr + 68 * s);
        const ulonglong2* su1 = (const ulonglong2*)(Sr + SROW + 68 * s);

        float x_cur = x_nxt;
        int tn = (t + 1 < T_DIM) ? (t + 1) : t;
        x_nxt = xp[(size_t)tn * (B_DIM * H_DIM)];

        unsigned long long a00 = 0ull, a01 = 0ull, a10 = 0ull, a11 = 0ull;

#pragma unroll
        for (int j2 = 0; j2 < 8; j2++) {
            ulonglong2 s0 = su0[j2];
            ulonglong2 s1 = su1[j2];
            ffma2(a00, s0.x, wrA[2 * j2]);     ffma2(a01, s0.x, wrB[2 * j2]);
            ffma2(a00, s0.y, wrA[2 * j2 + 1]); ffma2(a01, s0.y, wrB[2 * j2 + 1]);
            ffma2(a10, s1.x, wrA[2 * j2]);     ffma2(a11, s1.x, wrB[2 * j2]);
            ffma2(a10, s1.y, wrA[2 * j2 + 1]); ffma2(a11, s1.y, wrB[2 * j2 + 1]);
        }
#pragma unroll
        for (int j2 = 0; j2 < 8; j2++) {
            uint4 q = wq[j2];
            unsigned long long wA0 = bf2f2(q.x);
            unsigned long long wB0 = bf2f2(q.y);
            unsigned long long wA1 = bf2f2(q.z);
            unsigned long long wB1 = bf2f2(q.w);
            ulonglong2 s0 = su0[8 + j2];
            ulonglong2 s1 = su1[8 + j2];
            ffma2(a00, s0.x, wA0); ffma2(a01, s0.x, wB0);
            ffma2(a00, s0.y, wA1); ffma2(a01, s0.y, wB1);
            ffma2(a10, s1.x, wA0); ffma2(a11, s1.x, wB0);
            ffma2(a10, s1.y, wA1); ffma2(a11, s1.y, wB1);
        }

        float f00 = hsum2(a00), f01 = hsum2(a01);
        float f10 = hsum2(a10), f11 = hsum2(a11);

        float m0 = sb0 ? f01 : f00;
        float m1 = sb0 ? f11 : f10;
        float o0 = sb0 ? f00 : f01;
        float o1 = sb0 ? f10 : f11;
        m0 += __shfl_xor_sync(0xffffffffu, o0, 8);
        m1 += __shfl_xor_sync(0xffffffffu, o1, 8);
        float mm = sb1 ? m1 : m0;
        float oo = sb1 ? m0 : m1;
        mm += __shfl_xor_sync(0xffffffffu, oo, 16);

        float h = fast_tanh(mm + x_cur);

        Sw[stoff] = h;
        outp[(size_t)t * (B_DIM * H_DIM)] = h;

        __syncthreads();
    };

#pragma unroll 1
    for (int t = 0; t < T_DIM; t += 2) {
        step(t,     S0, S1);
        step(t + 1, S1, S0);
    }

    if (write_state) *state_out = S0[stoff];
}

// ---------------------------------------------------------------------------
// Launch
// ---------------------------------------------------------------------------
extern "C" void kernel_launch(void* const* d_in, const int* in_sizes, int n_in,
                              void* d_out, int out_size)
{
    (void)n_in; (void)in_sizes;
    const float* inputs = (const float*)d_in[0];  // [T,B,I]
    const float* W_xh   = (const float*)d_in[1];  // [I,H]
    const float* W_hh   = (const float*)d_in[2];  // [H,H]
    const float* b_h    = (const float*)d_in[3];  // [H]
    float* out = (float*)d_out;

    const long long need = (long long)T_DIM * B_DIM * H_DIM + (long long)B_DIM * H_DIM;
    int write_state = ((long long)out_size >= need) ? 1 : 0;

    dim3 g1(M_DIM / GBM, H_DIM / GBN);
    gemm_xh_tc<<<g1, 256>>>(inputs, W_xh, b_h);

    cudaFuncSetAttribute(rnn_kernel, cudaFuncAttributeMaxDynamicSharedMemorySize,
                         RNN_SMEM_B);
    rnn_kernel<<<B_DIM / 2, 512, RNN_SMEM_B>>>(W_hh, out, write_state);
}

// round 12
// speedup vs baseline: 1.1391x; 1.0204x over previous
#include <cuda_runtime.h>
#include <cuda_bf16.h>
#include <mma.h>
#include <cstdint>

using namespace nvcuda;

// Problem constants (fixed by the reference)
#define T_DIM 1024
#define B_DIM 256
#define I_DIM 256
#define H_DIM 256
#define M_DIM (T_DIM * B_DIM)

// Scratch: X = inputs @ W_xh + b_h  (fp32, 268 MB)
__device__ float g_X[(size_t)M_DIM * H_DIM];
// Pre-converted weight splits (bf16 hi + lo), written once by prep kernel
__device__ __nv_bfloat16 g_Whi[I_DIM * H_DIM];
__device__ __nv_bfloat16 g_Wlo[I_DIM * H_DIM];

// ---------------------------------------------------------------------------
// packed helpers
// ---------------------------------------------------------------------------
__device__ __forceinline__ void ffma2(unsigned long long& d,
                                      unsigned long long a,
                                      unsigned long long b) {
    asm("fma.rn.f32x2 %0, %1, %2, %0;" : "+l"(d) : "l"(a), "l"(b));
}
__device__ __forceinline__ unsigned long long pk2(float lo, float hi) {
    unsigned long long d;
    asm("mov.b64 %0, {%1, %2};" : "=l"(d) : "f"(lo), "f"(hi));
    return d;
}
__device__ __forceinline__ float2 upk2(unsigned long long a) {
    float2 v;
    asm("mov.b64 {%0, %1}, %2;" : "=f"(v.x), "=f"(v.y) : "l"(a));
    return v;
}
__device__ __forceinline__ float hsum2(unsigned long long a) {
    float2 v = upk2(a);
    return v.x + v.y;
}
__device__ __forceinline__ unsigned long long bf2f2(uint32_t b) {
    uint32_t lo = b << 16;
    uint32_t hi = b & 0xffff0000u;
    unsigned long long d;
    asm("mov.b64 %0, {%1, %2};" : "=l"(d) : "r"(lo), "r"(hi));
    return d;
}
__device__ __forceinline__ uint32_t f2bf2(float lo, float hi) {
    uint32_t d;
    asm("cvt.rn.bf16x2.f32 %0, %1, %2;" : "=r"(d) : "f"(hi), "f"(lo));
    return d;
}
__device__ __forceinline__ float fast_tanh(float x) {
    float e, r;
    asm("ex2.approx.f32 %0, %1;" : "=f"(e) : "f"(x * 2.8853900817779268f));
    asm("rcp.approx.f32 %0, %1;" : "=f"(r) : "f"(e + 1.0f));
    return (e - 1.0f) * r;
}

// split 16 consecutive fp32 -> 8 bf16x2 hi + 8 bf16x2 lo, written as 2+2 uint4
__device__ __forceinline__ void split16(const float* v, uint4* hiOut, uint4* loOut) {
    uint32_t h[8], l[8];
#pragma unroll
    for (int j = 0; j < 8; j++) {
        float a0 = v[2 * j], a1 = v[2 * j + 1];
        uint32_t hp = f2bf2(a0, a1);
        float2 hv = upk2(bf2f2(hp));
        l[j] = f2bf2(a0 - hv.x, a1 - hv.y);
        h[j] = hp;
    }
    hiOut[0] = make_uint4(h[0], h[1], h[2], h[3]);
    hiOut[1] = make_uint4(h[4], h[5], h[6], h[7]);
    loOut[0] = make_uint4(l[0], l[1], l[2], l[3]);
    loOut[1] = make_uint4(l[4], l[5], l[6], l[7]);
}

// ---------------------------------------------------------------------------
// Kernel 0: one-time hi/lo split of W_xh (same values the inline split made)
// 64 CTAs x 256 threads, 4 fp32 each.
// ---------------------------------------------------------------------------
__global__ __launch_bounds__(256) void prep_w(const float* __restrict__ W) {
    int i = blockIdx.x * 256 + threadIdx.x;     // 0..16383
    float4 w = *(const float4*)&W[i * 4];
    uint32_t h0 = f2bf2(w.x, w.y), h1 = f2bf2(w.z, w.w);
    float2 v0 = upk2(bf2f2(h0)), v1 = upk2(bf2f2(h1));
    uint32_t l0 = f2bf2(w.x - v0.x, w.y - v0.y);
    uint32_t l1 = f2bf2(w.z - v1.x, w.w - v1.y);
    ((uint2*)g_Whi)[i] = make_uint2(h0, h1);
    ((uint2*)g_Wlo)[i] = make_uint2(l0, l1);
}

// ---------------------------------------------------------------------------
// Kernel 1: X = inputs @ W_xh + b_h  — wmma bf16 3-term, B RESIDENT IN SMEM.
// CTA 256 thr, tile 128x128. The CTA's full 256x128 W hi/lo slices live in
// smem (139KB, L2-served); k-loop only streams & converts A (ping-pong bufs,
// one barrier per 32-k tile). X ~= Ahi*Whi + Ahi*Wlo + Alo*Whi, fp32 acc.
// ---------------------------------------------------------------------------
#define GBM 128
#define GBN 128
#define GBK 32
#define ALD 48     // A tile leading dim (32 data + 16 pad bf16)
#define BLD 136    // B slab leading dim (128 data + 8 pad bf16)

#define OFF_BHI 0
#define OFF_BLO (I_DIM * BLD * 2)                    // 69632
#define OFF_A   (2 * I_DIM * BLD * 2)                // 139264
#define ABUF_B  (GBM * ALD * 2)                      // 12288 bytes per hi/lo buf
#define GEMM_SMEM_B (OFF_A + 4 * ABUF_B)             // 188416

__global__ __launch_bounds__(256) void gemm_xh_tc(
    const float* __restrict__ A,     // [M_DIM, I_DIM]
    const float* __restrict__ bias)  // [H_DIM]
{
    extern __shared__ char gsm[];
    __nv_bfloat16* sBhi = (__nv_bfloat16*)(gsm + OFF_BHI);   // [256][BLD]
    __nv_bfloat16* sBlo = (__nv_bfloat16*)(gsm + OFF_BLO);   // [256][BLD]
    // A ping-pong: buf b hi at OFF_A + (2b)*ABUF_B, lo at OFF_A + (2b+1)*ABUF_B
    __nv_bfloat16* sAhi[2] = {(__nv_bfloat16*)(gsm + OFF_A),
                              (__nv_bfloat16*)(gsm + OFF_A + 2 * ABUF_B)};
    __nv_bfloat16* sAlo[2] = {(__nv_bfloat16*)(gsm + OFF_A + ABUF_B),
                              (__nv_bfloat16*)(gsm + OFF_A + 3 * ABUF_B)};

    const int mTile = blockIdx.x;
    const int nTile = blockIdx.y;
    const int tid = threadIdx.x;
    const int wid = tid >> 5;
    const int wm = wid & 3;          // 32-row block
    const int wn = wid >> 2;         // 64-col block

    const int aRow = tid >> 1;
    const int aCol = (tid & 1) * 16;
    const float* Ag = A + (size_t)mTile * GBM * I_DIM;

    // ---- bias -> accumulators (staged in the A-buffer region)
    float* sBiasF = (float*)(gsm + OFF_A);
    for (int idx = tid; idx < 16 * GBN; idx += 256) {
        int r = idx >> 7, c = idx & 127;
        sBiasF[r * BLD + c] = bias[nTile * GBN + c];
    }
    __syncthreads();
    wmma::fragment<wmma::accumulator, 16, 16, 16, float> acc[2][4];
#pragma unroll
    for (int i = 0; i < 2; i++)
#pragma unroll
        for (int j = 0; j < 4; j++)
            wmma::load_matrix_sync(acc[i][j], &sBiasF[wn * 64 + j * 16], BLD,
                                   wmma::mem_row_major);
    __syncthreads();

    // ---- load resident B slices (hi+lo), 16 uint4 per thread each
    {
        const uint4* gh = (const uint4*)(g_Whi + nTile * GBN);
        const uint4* gl = (const uint4*)(g_Wlo + nTile * GBN);
        // global row stride in uint4: 256 bf16 = 32 uint4
        for (int idx = tid; idx < I_DIM * 16; idx += 256) {
            int row = idx >> 4;          // 0..255
            int c8 = (idx & 15);         // uint4 index within 128 cols
            uint4 vh = gh[row * 32 + c8];
            uint4 vl = gl[row * 32 + c8];
            *(uint4*)&sBhi[row * BLD + c8 * 8] = vh;
            *(uint4*)&sBlo[row * BLD + c8 * 8] = vl;
        }
    }

    // ---- preload A tile 0 (convert + store)
    {
        float av[16];
        *(float4*)&av[0]  = *(const float4*)&Ag[(size_t)aRow * I_DIM + aCol + 0];
        *(float4*)&av[4]  = *(const float4*)&Ag[(size_t)aRow * I_DIM + aCol + 4];
        *(float4*)&av[8]  = *(const float4*)&Ag[(size_t)aRow * I_DIM + aCol + 8];
        *(float4*)&av[12] = *(const float4*)&Ag[(size_t)aRow * I_DIM + aCol + 12];
        split16(av, (uint4*)&sAhi[0][aRow * ALD + aCol],
                    (uint4*)&sAlo[0][aRow * ALD + aCol]);
    }
    __syncthreads();

#pragma unroll 1
    for (int kt = 0; kt < I_DIM / GBK; kt++) {
        const int cur = kt & 1;

        // prefetch next A tile (global -> regs)
        float av[16];
        if (kt + 1 < I_DIM / GBK) {
            int k0 = (kt + 1) * GBK;
            *(float4*)&av[0]  = *(const float4*)&Ag[(size_t)aRow * I_DIM + k0 + aCol + 0];
            *(float4*)&av[4]  = *(const float4*)&Ag[(size_t)aRow * I_DIM + k0 + aCol + 4];
            *(float4*)&av[8]  = *(const float4*)&Ag[(size_t)aRow * I_DIM + k0 + aCol + 8];
            *(float4*)&av[12] = *(const float4*)&Ag[(size_t)aRow * I_DIM + k0 + aCol + 12];
        }

        // compute current tile
#pragma unroll
        for (int ks = 0; ks < 2; ks++) {
            const int kg = kt * GBK + ks * 16;   // global k of this 16-chunk
            wmma::fragment<wmma::matrix_a, 16, 16, 16, __nv_bfloat16, wmma::row_major> afh[2], afl[2];
            wmma::fragment<wmma::matrix_b, 16, 16, 16, __nv_bfloat16, wmma::row_major> bfh[4], bfl[4];
#pragma unroll
            for (int i = 0; i < 2; i++) {
                wmma::load_matrix_sync(afh[i], &sAhi[cur][(wm * 32 + i * 16) * ALD + ks * 16], ALD);
                wmma::load_matrix_sync(afl[i], &sAlo[cur][(wm * 32 + i * 16) * ALD + ks * 16], ALD);
            }
#pragma unroll
            for (int j = 0; j < 4; j++) {
                wmma::load_matrix_sync(bfh[j], &sBhi[kg * BLD + wn * 64 + j * 16], BLD);
                wmma::load_matrix_sync(bfl[j], &sBlo[kg * BLD + wn * 64 + j * 16], BLD);
            }
#pragma unroll
            for (int i = 0; i < 2; i++)
#pragma unroll
                for (int j = 0; j < 4; j++) {
                    wmma::mma_sync(acc[i][j], afh[i], bfh[j], acc[i][j]);
                    wmma::mma_sync(acc[i][j], afh[i], bfl[j], acc[i][j]);
                    wmma::mma_sync(acc[i][j], afl[i], bfh[j], acc[i][j]);
                }
        }

        // convert & store prefetched tile into the other buffer
        if (kt + 1 < I_DIM / GBK) {
            const int nxt = cur ^ 1;
            split16(av, (uint4*)&sAhi[nxt][aRow * ALD + aCol],
                        (uint4*)&sAlo[nxt][aRow * ALD + aCol]);
            __syncthreads();
        }
    }

    // store accumulators (bias already folded in)
#pragma unroll
    for (int i = 0; i < 2; i++)
#pragma unroll
        for (int j = 0; j < 4; j++) {
            size_t row0 = (size_t)mTile * GBM + wm * 32 + i * 16;
            int col0 = nTile * GBN + wn * 64 + j * 16;
            wmma::store_matrix_sync(&g_X[row0 * H_DIM + col0], acc[i][j], H_DIM,
                                    wmma::mem_row_major);
        }
}

// ---------------------------------------------------------------------------
// Kernel 2: the recurrence — EXACT round-8 version (measured ~1088us).
// ---------------------------------------------------------------------------
#define SROW 272
#define BUF_F (2 * SROW)
#define PAIR_STRIDE_U32 36
#define SPLIT_STRIDE_U32 (128 * PAIR_STRIDE_U32 + 4)
#define SMEM_STATE_F (2 * BUF_F)
#define RNN_SMEM_F (SMEM_STATE_F + 4 * SPLIT_STRIDE_U32)
#define RNN_SMEM_B (RNN_SMEM_F * 4)

__global__ __launch_bounds__(512, 1) void rnn_kernel(
    const float* __restrict__ W,
    float* __restrict__ out,
    int write_state)
{
    extern __shared__ float sm[];
    float* S0 = sm;
    float* S1 = sm + BUF_F;
    uint32_t* WB = (uint32_t*)(sm + SMEM_STATE_F);

    const int tid = threadIdx.x;
    const int wid = tid >> 5;
    const int lane = tid & 31;
    const int p = wid * 8 + (lane & 7);
    const int s = lane >> 3;
    const int h0 = 2 * p;
    const int kbase = 64 * s;
    const int bidx0 = blockIdx.x * 2;
    const int hs = h0 + ((h0 >> 6) << 2);
    const bool sb0 = (s & 1);
    const int sb1 = (s >> 1);

    unsigned long long wrA[16], wrB[16];
#pragma unroll
    for (int j = 0; j < 16; j++) {
        int k = kbase + 2 * j;
        float2 wk  = *(const float2*)&W[(size_t)k * H_DIM + h0];
        float2 wk1 = *(const float2*)&W[(size_t)(k + 1) * H_DIM + h0];
        wrA[j] = pk2(wk.x, wk1.x);
        wrB[j] = pk2(wk.y, wk1.y);
    }

    uint32_t* myWB = WB + s * SPLIT_STRIDE_U32 + p * PAIR_STRIDE_U32;
#pragma unroll
    for (int j = 0; j < 16; j++) {
        int k = kbase + 32 + 2 * j;
        float2 wk  = *(const float2*)&W[(size_t)k * H_DIM + h0];
        float2 wk1 = *(const float2*)&W[(size_t)(k + 1) * H_DIM + h0];
        myWB[2 * j]     = f2bf2(wk.x, wk1.x);
        myWB[2 * j + 1] = f2bf2(wk.y, wk1.y);
    }

    for (int i = tid; i < SMEM_STATE_F; i += 512) sm[i] = 0.0f;
    __syncthreads();

    const uint4* wq = (const uint4*)myWB;
    const int stoff = sb1 * SROW + hs + (sb0 ? 1 : 0);
    const size_t goff = (size_t)(bidx0 + sb1) * H_DIM + h0 + (sb0 ? 1 : 0);
    float* outp = out + goff;
    const float* xp = g_X + goff;
    float* state_out = out + (size_t)T_DIM * B_DIM * H_DIM + goff;

    float x_nxt = *xp;

    auto step = [&](int t, const float* Sr, float* Sw) {
        const ulonglong2* su0 = (const ulonglong2*)(Sr + 68 * s);
        const ulonglong2* su1 = (const ulonglong2*)(Sr + SROW + 68 * s);

        float x_cur = x_nxt;
        int tn = (t + 1 < T_DIM) ? (t + 1) : t;
        x_nxt = xp[(size_t)tn * (B_DIM * H_DIM)];

        unsigned long long a00 = 0ull, a01 = 0ull, a10 = 0ull, a11 = 0ull;

#pragma unroll
        for (int j2 = 0; j2 < 8; j2++) {
            ulonglong2 s0 = su0[j2];
            ulonglong2 s1 = su1[j2];
            ffma2(a00, s0.x, wrA[2 * j2]);     ffma2(a01, s0.x, wrB[2 * j2]);
            ffma2(a00, s0.y, wrA[2 * j2 + 1]); ffma2(a01, s0.y, wrB[2 * j2 + 1]);
            ffma2(a10, s1.x, wrA[2 * j2]);     ffma2(a11, s1.x, wrB[2 * j2]);
            ffma2(a10, s1.y, wrA[2 * j2 + 1]); ffma2(a11, s1.y, wrB[2 * j2 + 1]);
        }
#pragma unroll
        for (int j2 = 0; j2 < 8; j2++) {
            uint4 q = wq[j2];
            unsigned long long wA0 = bf2f2(q.x);
            unsigned long long wB0 = bf2f2(q.y);
            unsigned long long wA1 = bf2f2(q.z);
            unsigned long long wB1 = bf2f2(q.w);
            ulonglong2 s0 = su0[8 + j2];
            ulonglong2 s1 = su1[8 + j2];
            ffma2(a00, s0.x, wA0); ffma2(a01, s0.x, wB0);
            ffma2(a00, s0.y, wA1); ffma2(a01, s0.y, wB1);
            ffma2(a10, s1.x, wA0); ffma2(a11, s1.x, wB0);
            ffma2(a10, s1.y, wA1); ffma2(a11, s1.y, wB1);
        }

        float f00 = hsum2(a00), f01 = hsum2(a01);
        float f10 = hsum2(a10), f11 = hsum2(a11);

        float m0 = sb0 ? f01 : f00;
        float m1 = sb0 ? f11 : f10;
        float o0 = sb0 ? f00 : f01;
        float o1 = sb0 ? f10 : f11;
        m0 += __shfl_xor_sync(0xffffffffu, o0, 8);
        m1 += __shfl_xor_sync(0xffffffffu, o1, 8);
        float mm = sb1 ? m1 : m0;
        float oo = sb1 ? m0 : m1;
        mm += __shfl_xor_sync(0xffffffffu, oo, 16);

        float h = fast_tanh(mm + x_cur);

        Sw[stoff] = h;
        outp[(size_t)t * (B_DIM * H_DIM)] = h;

        __syncthreads();
    };

#pragma unroll 1
    for (int t = 0; t < T_DIM; t += 2) {
        step(t,     S0, S1);
        step(t + 1, S1, S0);
    }

    if (write_state) *state_out = S0[stoff];
}

// ---------------------------------------------------------------------------
// Launch
// ---------------------------------------------------------------------------
extern "C" void kernel_launch(void* const* d_in, const int* in_sizes, int n_in,
                              void* d_out, int out_size)
{
    (void)n_in; (void)in_sizes;
    const float* inputs = (const float*)d_in[0];  // [T,B,I]
    const float* W_xh   = (const float*)d_in[1];  // [I,H]
    const float* W_hh   = (const float*)d_in[2];  // [H,H]
    const float* b_h    = (const float*)d_in[3];  // [H]
    float* out = (float*)d_out;

    const long long need = (long long)T_DIM * B_DIM * H_DIM + (long long)B_DIM * H_DIM;
    int write_state = ((long long)out_size >= need) ? 1 : 0;

    prep_w<<<64, 256>>>(W_xh);

    cudaFuncSetAttribute(gemm_xh_tc, cudaFuncAttributeMaxDynamicSharedMemorySize,
                         GEMM_SMEM_B);
    dim3 g1(M_DIM / GBM, H_DIM / GBN);
    gemm_xh_tc<<<g1, 256, GEMM_SMEM_B>>>(inputs, b_h);

    cudaFuncSetAttribute(rnn_kernel, cudaFuncAttributeMaxDynamicSharedMemorySize,
                         RNN_SMEM_B);
    rnn_kernel<<<B_DIM / 2, 512, RNN_SMEM_B>>>(W_hh, out, write_state);
}

// round 14
// speedup vs baseline: 1.1529x; 1.0121x over previous
#include <cuda_runtime.h>
#include <cuda_bf16.h>
#include <mma.h>
#include <cstdint>

using namespace nvcuda;

// Problem constants (fixed by the reference)
#define T_DIM 1024
#define B_DIM 256
#define I_DIM 256
#define H_DIM 256
#define M_DIM (T_DIM * B_DIM)

// Scratch: X = inputs @ W_xh + b_h  (fp32, 268 MB)
__device__ float g_X[(size_t)M_DIM * H_DIM];
// Pre-split weights (bf16 hi + lo), [k][n] layout, written once by prep kernel
__device__ __nv_bfloat16 g_Whi[I_DIM * H_DIM];
__device__ __nv_bfloat16 g_Wlo[I_DIM * H_DIM];

// ---------------------------------------------------------------------------
// packed helpers
// ---------------------------------------------------------------------------
__device__ __forceinline__ void ffma2(unsigned long long& d,
                                      unsigned long long a,
                                      unsigned long long b) {
    asm("fma.rn.f32x2 %0, %1, %2, %0;" : "+l"(d) : "l"(a), "l"(b));
}
__device__ __forceinline__ unsigned long long pk2(float lo, float hi) {
    unsigned long long d;
    asm("mov.b64 %0, {%1, %2};" : "=l"(d) : "f"(lo), "f"(hi));
    return d;
}
__device__ __forceinline__ float2 upk2(unsigned long long a) {
    float2 v;
    asm("mov.b64 {%0, %1}, %2;" : "=f"(v.x), "=f"(v.y) : "l"(a));
    return v;
}
__device__ __forceinline__ float hsum2(unsigned long long a) {
    float2 v = upk2(a);
    return v.x + v.y;
}
__device__ __forceinline__ unsigned long long bf2f2(uint32_t b) {
    uint32_t lo = b << 16;
    uint32_t hi = b & 0xffff0000u;
    unsigned long long d;
    asm("mov.b64 %0, {%1, %2};" : "=l"(d) : "r"(lo), "r"(hi));
    return d;
}
__device__ __forceinline__ uint32_t f2bf2(float lo, float hi) {
    uint32_t d;
    asm("cvt.rn.bf16x2.f32 %0, %1, %2;" : "=r"(d) : "f"(hi), "f"(lo));
    return d;
}
__device__ __forceinline__ float fast_tanh(float x) {
    float e, r;
    asm("ex2.approx.f32 %0, %1;" : "=f"(e) : "f"(x * 2.8853900817779268f));
    asm("rcp.approx.f32 %0, %1;" : "=f"(r) : "f"(e + 1.0f));
    return (e - 1.0f) * r;
}

// split 16 consecutive fp32 -> 8 bf16x2 hi + 8 bf16x2 lo, written as 2+2 uint4
__device__ __forceinline__ void split16(const float* v, uint4* hiOut, uint4* loOut) {
    uint32_t h[8], l[8];
#pragma unroll
    for (int j = 0; j < 8; j++) {
        float a0 = v[2 * j], a1 = v[2 * j + 1];
        uint32_t hp = f2bf2(a0, a1);
        float2 hv = upk2(bf2f2(hp));
        l[j] = f2bf2(a0 - hv.x, a1 - hv.y);
        h[j] = hp;
    }
    hiOut[0] = make_uint4(h[0], h[1], h[2], h[3]);
    hiOut[1] = make_uint4(h[4], h[5], h[6], h[7]);
    loOut[0] = make_uint4(l[0], l[1], l[2], l[3]);
    loOut[1] = make_uint4(l[4], l[5], l[6], l[7]);
}

// ---------------------------------------------------------------------------
// Kernel 0: one-time hi/lo split of W_xh ([k][n] layout kept). 64x256 thr.
// ---------------------------------------------------------------------------
__global__ __launch_bounds__(256) void prep_w(const float* __restrict__ W) {
    int i = blockIdx.x * 256 + threadIdx.x;     // 0..16383
    float4 w = *(const float4*)&W[i * 4];
    uint32_t h0 = f2bf2(w.x, w.y), h1 = f2bf2(w.z, w.w);
    float2 v0 = upk2(bf2f2(h0)), v1 = upk2(bf2f2(h1));
    uint32_t l0 = f2bf2(w.x - v0.x, w.y - v0.y);
    uint32_t l1 = f2bf2(w.z - v1.x, w.w - v1.y);
    ((uint2*)g_Whi)[i] = make_uint2(h0, h1);
    ((uint2*)g_Wlo)[i] = make_uint2(l0, l1);
}

// ---------------------------------------------------------------------------
// Kernel 1: X = inputs @ W_xh + b_h — wmma bf16 3-term, 2 CTAs/SM.
// CTA 256 thr, tile 128(M) x 64(N). Resident B slice (256x64 hi+lo, 73.7KB)
// + SINGLE 32-k A buffer (24.6KB) => 98.3KB smem => 2 CTAs/SM, 8 warps/SMSP
// (the co-resident CTA provides the latency hiding a double buffer would).
// Warp = 32x32 tile. X ~= Ahi*Whi + Ahi*Wlo + Alo*Whi, fp32 accumulate.
// ---------------------------------------------------------------------------
#define GBM 128
#define GBN 64
#define GBK 32
#define NCHUNK (I_DIM / GBK)   // 8
#define ALD 48                 // A leading dim bf16 (32 data + 16 pad), 96B rows
#define BLD 72                 // B leading dim bf16 (64 data + 8 pad), 144B rows

#define OFF_BHI 0
#define OFF_BLO (I_DIM * BLD * 2)          // 36864
#define OFF_A   (2 * I_DIM * BLD * 2)      // 73728
#define A_COMP  (GBM * ALD * 2)            // 12288
#define G_SMEM  (OFF_A + 2 * A_COMP)       // 98304

__global__ __launch_bounds__(256, 2) void gemm_xh_tc(
    const float* __restrict__ A,     // [M_DIM, I_DIM]
    const float* __restrict__ bias)  // [H_DIM]
{
    extern __shared__ char gsm[];
    __nv_bfloat16* sBhi = (__nv_bfloat16*)(gsm + OFF_BHI);   // [256][BLD]
    __nv_bfloat16* sBlo = (__nv_bfloat16*)(gsm + OFF_BLO);   // [256][BLD]
    __nv_bfloat16* sAhi = (__nv_bfloat16*)(gsm + OFF_A);     // [128][ALD]
    __nv_bfloat16* sAlo = (__nv_bfloat16*)(gsm + OFF_A + A_COMP);

    const int mTile = blockIdx.x;
    const int nTile = blockIdx.y;
    const int tid = threadIdx.x;
    const int wid = tid >> 5;
    const int wm = wid & 3;          // 32-row block
    const int wn = wid >> 2;         // 32-col block

    // A tile: 128 rows x 32 k; thread loads 16 floats
    const int aRow = tid >> 1;
    const int aCol = (tid & 1) * 16;
    const float* Ag = A + (size_t)mTile * GBM * I_DIM;

    // ---- bias -> accumulators (staged in the A region)
    float* sBiasF = (float*)(gsm + OFF_A);   // 16 x BLD floats = 4608B
    for (int idx = tid; idx < 16 * GBN; idx += 256) {
        int r = idx >> 6, c = idx & 63;
        sBiasF[r * BLD + c] = bias[nTile * GBN + c];
    }
    __syncthreads();
    wmma::fragment<wmma::accumulator, 16, 16, 16, float> acc[2][2];
#pragma unroll
    for (int i = 0; i < 2; i++)
#pragma unroll
        for (int j = 0; j < 2; j++)
            wmma::load_matrix_sync(acc[i][j], &sBiasF[wn * 32 + j * 16], BLD,
                                   wmma::mem_row_major);

    // ---- load resident B slice (hi+lo): 256 k-rows x 64 cols
    {
        const uint4* gh = (const uint4*)g_Whi;   // row stride 32 uint4
        const uint4* gl = (const uint4*)g_Wlo;
        const int cbase = nTile * 8;             // 64 cols = 8 uint4
#pragma unroll
        for (int idx = tid; idx < 2048; idx += 256) {
            int row = idx >> 3;
            int q = idx & 7;
            uint4 vh = gh[row * 32 + cbase + q];
            uint4 vl = gl[row * 32 + cbase + q];
            *(uint4*)&sBhi[row * BLD + q * 8] = vh;
            *(uint4*)&sBlo[row * BLD + q * 8] = vl;
        }
    }

    // preload A chunk 0 into regs
    float av[16];
    *(float4*)&av[0]  = *(const float4*)&Ag[(size_t)aRow * I_DIM + aCol + 0];
    *(float4*)&av[4]  = *(const float4*)&Ag[(size_t)aRow * I_DIM + aCol + 4];
    *(float4*)&av[8]  = *(const float4*)&Ag[(size_t)aRow * I_DIM + aCol + 8];
    *(float4*)&av[12] = *(const float4*)&Ag[(size_t)aRow * I_DIM + aCol + 12];

    __syncthreads();   // bias reads + B stores complete

#pragma unroll 1
    for (int ck = 0; ck < NCHUNK; ck++) {
        // write chunk ck into the (single) A buffer
        split16(av, (uint4*)&sAhi[aRow * ALD + aCol],
                    (uint4*)&sAlo[aRow * ALD + aCol]);

        // start loading chunk ck+1 (overlaps this chunk's compute)
        if (ck + 1 < NCHUNK) {
            int k0 = (ck + 1) * GBK;
            *(float4*)&av[0]  = *(const float4*)&Ag[(size_t)aRow * I_DIM + k0 + aCol + 0];
            *(float4*)&av[4]  = *(const float4*)&Ag[(size_t)aRow * I_DIM + k0 + aCol + 4];
            *(float4*)&av[8]  = *(const float4*)&Ag[(size_t)aRow * I_DIM + k0 + aCol + 8];
            *(float4*)&av[12] = *(const float4*)&Ag[(size_t)aRow * I_DIM + k0 + aCol + 12];
        }

        __syncthreads();   // A stores visible

#pragma unroll
        for (int ks = 0; ks < 2; ks++) {
            const int kg = ck * GBK + ks * 16;
            wmma::fragment<wmma::matrix_a, 16, 16, 16, __nv_bfloat16, wmma::row_major> afh[2], afl[2];
            wmma::fragment<wmma::matrix_b, 16, 16, 16, __nv_bfloat16, wmma::row_major> bfh[2], bfl[2];
#pragma unroll
            for (int i = 0; i < 2; i++) {
                wmma::load_matrix_sync(afh[i], &sAhi[(wm * 32 + i * 16) * ALD + ks * 16], ALD);
                wmma::load_matrix_sync(afl[i], &sAlo[(wm * 32 + i * 16) * ALD + ks * 16], ALD);
            }
#pragma unroll
            for (int j = 0; j < 2; j++) {
                wmma::load_matrix_sync(bfh[j], &sBhi[kg * BLD + wn * 32 + j * 16], BLD);
                wmma::load_matrix_sync(bfl[j], &sBlo[kg * BLD + wn * 32 + j * 16], BLD);
            }
#pragma unroll
            for (int i = 0; i < 2; i++)
#pragma unroll
                for (int j = 0; j < 2; j++) {
                    wmma::mma_sync(acc[i][j], afh[i], bfh[j], acc[i][j]);
                    wmma::mma_sync(acc[i][j], afh[i], bfl[j], acc[i][j]);
                    wmma::mma_sync(acc[i][j], afl[i], bfh[j], acc[i][j]);
                }
        }

        __syncthreads();   // all frag reads done before next overwrite
    }

    // store accumulators (bias already folded in)
#pragma unroll
    for (int i = 0; i < 2; i++)
#pragma unroll
        for (int j = 0; j < 2; j++) {
            size_t row0 = (size_t)mTile * GBM + wm * 32 + i * 16;
            int col0 = nTile * GBN + wn * 32 + j * 16;
            wmma::store_matrix_sync(&g_X[row0 * H_DIM + col0], acc[i][j], H_DIM,
                                    wmma::mem_row_major);
        }
}

// ---------------------------------------------------------------------------
// Kernel 2: the recurrence — EXACT round-8 version (measured ~1088us).
// ---------------------------------------------------------------------------
#define SROW 272
#define BUF_F (2 * SROW)
#define PAIR_STRIDE_U32 36
#define SPLIT_STRIDE_U32 (128 * PAIR_STRIDE_U32 + 4)
#define SMEM_STATE_F (2 * BUF_F)
#define RNN_SMEM_F (SMEM_STATE_F + 4 * SPLIT_STRIDE_U32)
#define RNN_SMEM_B (RNN_SMEM_F * 4)

__global__ __launch_bounds__(512, 1) void rnn_kernel(
    const float* __restrict__ W,
    float* __restrict__ out,
    int write_state)
{
    extern __shared__ float sm[];
    float* S0 = sm;
    float* S1 = sm + BUF_F;
    uint32_t* WB = (uint32_t*)(sm + SMEM_STATE_F);

    const int tid = threadIdx.x;
    const int wid = tid >> 5;
    const int lane = tid & 31;
    const int p = wid * 8 + (lane & 7);
    const int s = lane >> 3;
    const int h0 = 2 * p;
    const int kbase = 64 * s;
    const int bidx0 = blockIdx.x * 2;
    const int hs = h0 + ((h0 >> 6) << 2);
    const bool sb0 = (s & 1);
    const int sb1 = (s >> 1);

    unsigned long long wrA[16], wrB[16];
#pragma unroll
    for (int j = 0; j < 16; j++) {
        int k = kbase + 2 * j;
        float2 wk  = *(const float2*)&W[(size_t)k * H_DIM + h0];
        float2 wk1 = *(const float2*)&W[(size_t)(k + 1) * H_DIM + h0];
        wrA[j] = pk2(wk.x, wk1.x);
        wrB[j] = pk2(wk.y, wk1.y);
    }

    uint32_t* myWB = WB + s * SPLIT_STRIDE_U32 + p * PAIR_STRIDE_U32;
#pragma unroll
    for (int j = 0; j < 16; j++) {
        int k = kbase + 32 + 2 * j;
        float2 wk  = *(const float2*)&W[(size_t)k * H_DIM + h0];
        float2 wk1 = *(const float2*)&W[(size_t)(k + 1) * H_DIM + h0];
        myWB[2 * j]     = f2bf2(wk.x, wk1.x);
        myWB[2 * j + 1] = f2bf2(wk.y, wk1.y);
    }

    for (int i = tid; i < SMEM_STATE_F; i += 512) sm[i] = 0.0f;
    __syncthreads();

    const uint4* wq = (const uint4*)myWB;
    const int stoff = sb1 * SROW + hs + (sb0 ? 1 : 0);
    const size_t goff = (size_t)(bidx0 + sb1) * H_DIM + h0 + (sb0 ? 1 : 0);
    float* outp = out + goff;
    const float* xp = g_X + goff;
    float* state_out = out + (size_t)T_DIM * B_DIM * H_DIM + goff;

    float x_nxt = *xp;

    auto step = [&](int t, const float* Sr, float* Sw) {
        const ulonglong2* su0 = (const ulonglong2*)(Sr + 68 * s);
        const ulonglong2* su1 = (const ulonglong2*)(Sr + SROW + 68 * s);

        float x_cur = x_nxt;
        int tn = (t + 1 < T_DIM) ? (t + 1) : t;
        x_nxt = xp[(size_t)tn * (B_DIM * H_DIM)];

        unsigned long long a00 = 0ull, a01 = 0ull, a10 = 0ull, a11 = 0ull;

#pragma unroll
        for (int j2 = 0; j2 < 8; j2++) {
            ulonglong2 s0 = su0[j2];
            ulonglong2 s1 = su1[j2];
            ffma2(a00, s0.x, wrA[2 * j2]);     ffma2(a01, s0.x, wrB[2 * j2]);
            ffma2(a00, s0.y, wrA[2 * j2 + 1]); ffma2(a01, s0.y, wrB[2 * j2 + 1]);
            ffma2(a10, s1.x, wrA[2 * j2]);     ffma2(a11, s1.x, wrB[2 * j2]);
            ffma2(a10, s1.y, wrA[2 * j2 + 1]); ffma2(a11, s1.y, wrB[2 * j2 + 1]);
        }
#pragma unroll
        for (int j2 = 0; j2 < 8; j2++) {
            uint4 q = wq[j2];
            unsigned long long wA0 = bf2f2(q.x);
            unsigned long long wB0 = bf2f2(q.y);
            unsigned long long wA1 = bf2f2(q.z);
            unsigned long long wB1 = bf2f2(q.w);
            ulonglong2 s0 = su0[8 + j2];
            ulonglong2 s1 = su1[8 + j2];
            ffma2(a00, s0.x, wA0); ffma2(a01, s0.x, wB0);
            ffma2(a00, s0.y, wA1); ffma2(a01, s0.y, wB1);
            ffma2(a10, s1.x, wA0); ffma2(a11, s1.x, wB0);
            ffma2(a10, s1.y, wA1); ffma2(a11, s1.y, wB1);
        }

        float f00 = hsum2(a00), f01 = hsum2(a01);
        float f10 = hsum2(a10), f11 = hsum2(a11);

        float m0 = sb0 ? f01 : f00;
        float m1 = sb0 ? f11 : f10;
        float o0 = sb0 ? f00 : f01;
        float o1 = sb0 ? f10 : f11;
        m0 += __shfl_xor_sync(0xffffffffu, o0, 8);
        m1 += __shfl_xor_sync(0xffffffffu, o1, 8);
        float mm = sb1 ? m1 : m0;
        float oo = sb1 ? m0 : m1;
        mm += __shfl_xor_sync(0xffffffffu, oo, 16);

        float h = fast_tanh(mm + x_cur);

        Sw[stoff] = h;
        outp[(size_t)t * (B_DIM * H_DIM)] = h;

        __syncthreads();
    };

#pragma unroll 1
    for (int t = 0; t < T_DIM; t += 2) {
        step(t,     S0, S1);
        step(t + 1, S1, S0);
    }

    if (write_state) *state_out = S0[stoff];
}

// ---------------------------------------------------------------------------
// Launch
// ---------------------------------------------------------------------------
extern "C" void kernel_launch(void* const* d_in, const int* in_sizes, int n_in,
                              void* d_out, int out_size)
{
    (void)n_in; (void)in_sizes;
    const float* inputs = (const float*)d_in[0];  // [T,B,I]
    const float* W_xh   = (const float*)d_in[1];  // [I,H]
    const float* W_hh   = (const float*)d_in[2];  // [H,H]
    const float* b_h    = (const float*)d_in[3];  // [H]
    float* out = (float*)d_out;

    const long long need = (long long)T_DIM * B_DIM * H_DIM + (long long)B_DIM * H_DIM;
    int write_state = ((long long)out_size >= need) ? 1 : 0;

    prep_w<<<64, 256>>>(W_xh);

    cudaFuncSetAttribute(gemm_xh_tc, cudaFuncAttributeMaxDynamicSharedMemorySize,
                         G_SMEM);
    dim3 g1(M_DIM / GBM, H_DIM / GBN);
    gemm_xh_tc<<<g1, 256, G_SMEM>>>(inputs, b_h);

    cudaFuncSetAttribute(rnn_kernel, cudaFuncAttributeMaxDynamicSharedMemorySize,
                         RNN_SMEM_B);
    rnn_kernel<<<B_DIM / 2, 512, RNN_SMEM_B>>>(W_hh, out, write_state);
}